// round 12
// baseline (speedup 1.0000x reference)
#include <cuda_runtime.h>
#include <cuda_fp16.h>
#include <cstdint>

// ---------------------------------------------------------------------------
// out[m, c] = sum_f sin(2*pi*f*t[m])*As[c,f] + cos(2*pi*f*t[m])*Ac[c,f]
// GEMM: M = 262144, N = 256, K = 256 (K = [sin | cos] halves).
// R12: R11 (register-synthesized A, 512 thr, 4 warps/SMSP, warp tile 32x64,
// no barriers) + SOFTWARE-PIPELINED A SYNTHESIS: A fragments for step ks+1
// are synthesized (MUFU) before the MMA chain of step ks, so the MUFU and
// tensor pipes issue concurrently inside each warp instead of alternating.
// A frags double-buffered (+8 regs); sincos packed immediately to fp16x2.
// ---------------------------------------------------------------------------

#define NT        512
#define MT        128                    // rows per CTA iteration
#define SF_OFF    131072
#define SMEM_TOTAL (131072 + 512)        // W (256x256 fp16) + freqs

static __device__ __forceinline__ uint32_t smem_u32(const void* p) {
    uint32_t a;
    asm("{ .reg .u64 t; cvta.to.shared.u64 t, %1; cvt.u32.u64 %0, t; }"
        : "=r"(a) : "l"(p));
    return a;
}

// byte offset of (row, 16B-chunk) in a 512 B/row tile with XOR swizzle:
// chunk' = chunk ^ (row & 7). Conflict-free for ldmatrix and the fills.
static __device__ __forceinline__ uint32_t swz(uint32_t row, uint32_t chunk) {
    return row * 512u + ((chunk ^ (row & 7u)) << 4);
}

#define LDSM_X4(r, addr) \
    asm volatile("ldmatrix.sync.aligned.m8n8.x4.shared.b16 {%0,%1,%2,%3}, [%4];" \
        : "=r"((r)[0]), "=r"((r)[1]), "=r"((r)[2]), "=r"((r)[3]) : "r"(addr))

#define MMA_16816(d, a, b0, b1) \
    asm volatile("mma.sync.aligned.m16n8k16.row.col.f32.f16.f16.f32 " \
        "{%0,%1,%2,%3}, {%4,%5,%6,%7}, {%8,%9}, {%0,%1,%2,%3};" \
        : "+f"((d)[0]), "+f"((d)[1]), "+f"((d)[2]), "+f"((d)[3]) \
        : "r"((a)[0]), "r"((a)[1]), "r"((a)[2]), "r"((a)[3]), \
          "r"(b0), "r"(b1))

static __device__ __forceinline__ uint32_t packh2(float x, float y) {
    __half2 h = __floats2half2_rn(x, y);
    return *reinterpret_cast<uint32_t*>(&h);
}

// synthesize the m16n8k16 A fragments for one k-step into a[2][4]
// rows: lane gid + {0,8,16,24}; freq cols per PTX layout {0,1,8,9}+16*kf+2*tig
static __device__ __forceinline__ void synthA(uint32_t a[2][4], const float* fq,
                                              int kf, bool useCos,
                                              float tv0, float tv1,
                                              float tv2, float tv3)
{
    const float Fa = fq[kf * 16 + 0], Fb = fq[kf * 16 + 1];
    const float Fc = fq[kf * 16 + 8], Fd = fq[kf * 16 + 9];
    if (!useCos) {
        a[0][0] = packh2(__sinf(tv0 * Fa), __sinf(tv0 * Fb));
        a[0][2] = packh2(__sinf(tv0 * Fc), __sinf(tv0 * Fd));
        a[0][1] = packh2(__sinf(tv1 * Fa), __sinf(tv1 * Fb));
        a[0][3] = packh2(__sinf(tv1 * Fc), __sinf(tv1 * Fd));
        a[1][0] = packh2(__sinf(tv2 * Fa), __sinf(tv2 * Fb));
        a[1][2] = packh2(__sinf(tv2 * Fc), __sinf(tv2 * Fd));
        a[1][1] = packh2(__sinf(tv3 * Fa), __sinf(tv3 * Fb));
        a[1][3] = packh2(__sinf(tv3 * Fc), __sinf(tv3 * Fd));
    } else {
        a[0][0] = packh2(__cosf(tv0 * Fa), __cosf(tv0 * Fb));
        a[0][2] = packh2(__cosf(tv0 * Fc), __cosf(tv0 * Fd));
        a[0][1] = packh2(__cosf(tv1 * Fa), __cosf(tv1 * Fb));
        a[0][3] = packh2(__cosf(tv1 * Fc), __cosf(tv1 * Fd));
        a[1][0] = packh2(__cosf(tv2 * Fa), __cosf(tv2 * Fb));
        a[1][2] = packh2(__cosf(tv2 * Fc), __cosf(tv2 * Fd));
        a[1][1] = packh2(__cosf(tv3 * Fa), __cosf(tv3 * Fb));
        a[1][3] = packh2(__cosf(tv3 * Fc), __cosf(tv3 * Fd));
    }
}

__global__ void __launch_bounds__(NT, 1)
fourier_mma_kernel(const float* __restrict__ t,
                   const float* __restrict__ freqs,
                   const float* __restrict__ As,
                   const float* __restrict__ Ac,
                   float* __restrict__ out,
                   int rows)
{
    extern __shared__ char smem[];
    char*  sW = smem;
    float* sF = (float*)(smem + SF_OFF);
    const uint32_t uW = smem_u32(sW);

    const int tid  = threadIdx.x;
    const int lane = tid & 31;
    const int wid  = tid >> 5;

    // ---- one-time: freqs (x 2pi) + W fp32->fp16 into swizzled SMEM --------
    if (tid < 128) sF[tid] = freqs[tid] * 6.283185307179586f;
    for (int i = tid; i < 256 * 64; i += NT) {
        const int n  = i >> 6;
        const int j4 = i & 63;
        const int k0 = j4 << 2;
        const float* src = (k0 < 128) ? (As + n * 128 + k0)
                                      : (Ac + n * 128 + (k0 - 128));
        const float4 w = *reinterpret_cast<const float4*>(src);
        uint32_t byte = swz((uint32_t)n, (uint32_t)(j4 >> 1)) + ((uint32_t)(j4 & 1) << 3);
        uint2 v;
        v.x = packh2(w.x, w.y);
        v.y = packh2(w.z, w.w);
        *reinterpret_cast<uint2*>(sW + byte) = v;
    }

    // ---- warp grid 4 (M) x 4 (N); warp tile 32 x 64 -----------------------
    const int wm  = wid >> 2;
    const int wn  = wid & 3;
    const int gid = lane >> 2, tig = lane & 3;
    const int bRowOff = (lane & 7) + ((lane >> 4) << 3);
    const int bHi     = (lane >> 3) & 1;
    const float* fq = sF + tig * 2;        // per-k-step: +16*kf, cols {0,1,8,9}

    const int numTiles = rows / MT;        // 2048
    const int stride   = gridDim.x;

    __syncthreads();                       // W + freqs visible

    for (int tile = blockIdx.x; tile < numTiles; tile += stride) {
        const int rbase = tile * MT + wm * 32 + gid;
        const float tv0 = t[rbase];
        const float tv1 = t[rbase + 8];
        const float tv2 = t[rbase + 16];
        const float tv3 = t[rbase + 24];

        float acc[2][8][4];
        #pragma unroll
        for (int mi = 0; mi < 2; mi++)
            #pragma unroll
            for (int ni = 0; ni < 8; ni++)
                #pragma unroll
                for (int q = 0; q < 4; q++) acc[mi][ni][q] = 0.0f;

        // A fragments double-buffered; synthesize step 0 up front
        uint32_t aB[2][2][4];
        synthA(aB[0], fq, 0, false, tv0, tv1, tv2, tv3);

        #pragma unroll
        for (int ks = 0; ks < 16; ks++) {
            const int cur = ks & 1;

            // ---- first B fragment (longest latency) -----------------------
            uint32_t bq[2][4];
            LDSM_X4(bq[0], uW + swz((uint32_t)(wn * 64 + bRowOff),
                                    (uint32_t)(ks * 2 + bHi)));

            // ---- synthesize NEXT step's A (independent of this step's MMA)
            if (ks < 15)
                synthA(aB[cur ^ 1], fq, (ks + 1) & 7, (ks + 1) >= 8,
                       tv0, tv1, tv2, tv3);

            // ---- 4 B tiles (16 N-cols each), ping-pong prefetch + MMA ------
            #pragma unroll
            for (int nt = 0; nt < 4; nt++) {
                if (nt < 3) {
                    const uint32_t n =
                        (uint32_t)(wn * 64 + (nt + 1) * 16 + bRowOff);
                    LDSM_X4(bq[(nt + 1) & 1],
                            uW + swz(n, (uint32_t)(ks * 2 + bHi)));
                }
                const uint32_t* bb = bq[nt & 1];
                #pragma unroll
                for (int mi = 0; mi < 2; mi++) {
                    MMA_16816(acc[mi][nt * 2],     aB[cur][mi], bb[0], bb[1]);
                    MMA_16816(acc[mi][nt * 2 + 1], aB[cur][mi], bb[2], bb[3]);
                }
            }
        }

        // ---- epilogue: regs -> gmem (STG.64) ------------------------------
        #pragma unroll
        for (int mi = 0; mi < 2; mi++) {
            const size_t mrow = (size_t)(rbase + mi * 16);
            float* o0 = out + mrow * 256 + wn * 64 + tig * 2;
            #pragma unroll
            for (int ni = 0; ni < 8; ni++) {
                float2 v0, v1;
                v0.x = acc[mi][ni][0]; v0.y = acc[mi][ni][1];
                v1.x = acc[mi][ni][2]; v1.y = acc[mi][ni][3];
                *reinterpret_cast<float2*>(o0 + ni * 8)        = v0;  // row r
                *reinterpret_cast<float2*>(o0 + ni * 8 + 2048) = v1;  // row r+8
            }
        }
    }
}

extern "C" void kernel_launch(void* const* d_in, const int* in_sizes, int n_in,
                              void* d_out, int out_size)
{
    const float* t     = (const float*)d_in[0];
    const float* freqs = (const float*)d_in[1];
    const float* As    = (const float*)d_in[2];
    const float* Ac    = (const float*)d_in[3];
    float* out         = (float*)d_out;

    int sm_count = 148;
    cudaDeviceGetAttribute(&sm_count, cudaDevAttrMultiProcessorCount, 0);
    cudaFuncSetAttribute(fourier_mma_kernel,
                         cudaFuncAttributeMaxDynamicSharedMemorySize, SMEM_TOTAL);

    const int rows = in_sizes[0];          // B*L = 262144
    fourier_mma_kernel<<<sm_count, NT, SMEM_TOTAL>>>(t, freqs, As, Ac, out, rows);
}

// round 13
// speedup vs baseline: 1.3130x; 1.3130x over previous
#include <cuda_runtime.h>
#include <cuda_fp16.h>
#include <cstdint>

// ---------------------------------------------------------------------------
// out[m, c] = sum_f sin(2*pi*f*t[m])*As[c,f] + cos(2*pi*f*t[m])*Ac[c,f]
// GEMM: M = 262144, N = 256, K = 256 (K = [sin | cos] halves).
// R13: R11 base (register-synthesized A, 512 thr, 4 warps/SMSP, warp tile
// 32x64, no barriers) + software-pipelined A synthesis (A[ks+1] MUFU burst
// issued before the MMA chain of A[ks]) — THIS TIME with the k-loop at
// #pragma unroll 2 (R12's regression came from full 16x unroll spilling at
// the 128-reg cap, not from the 16-reg double buffer). B uses a single
// bq[4] refilled per tile (saves 4 regs vs ping-pong; the gap is covered
// by the interleaved synthA).
// ---------------------------------------------------------------------------

#define NT        512
#define MT        128                    // rows per CTA iteration
#define SF_OFF    131072
#define SMEM_TOTAL (131072 + 512)        // W (256x256 fp16) + freqs

static __device__ __forceinline__ uint32_t smem_u32(const void* p) {
    uint32_t a;
    asm("{ .reg .u64 t; cvta.to.shared.u64 t, %1; cvt.u32.u64 %0, t; }"
        : "=r"(a) : "l"(p));
    return a;
}

// byte offset of (row, 16B-chunk) in a 512 B/row tile with XOR swizzle:
// chunk' = chunk ^ (row & 7). Conflict-free for ldmatrix and the fills.
static __device__ __forceinline__ uint32_t swz(uint32_t row, uint32_t chunk) {
    return row * 512u + ((chunk ^ (row & 7u)) << 4);
}

#define LDSM_X4(r, addr) \
    asm volatile("ldmatrix.sync.aligned.m8n8.x4.shared.b16 {%0,%1,%2,%3}, [%4];" \
        : "=r"((r)[0]), "=r"((r)[1]), "=r"((r)[2]), "=r"((r)[3]) : "r"(addr))

#define MMA_16816(d, a, b0, b1) \
    asm volatile("mma.sync.aligned.m16n8k16.row.col.f32.f16.f16.f32 " \
        "{%0,%1,%2,%3}, {%4,%5,%6,%7}, {%8,%9}, {%0,%1,%2,%3};" \
        : "+f"((d)[0]), "+f"((d)[1]), "+f"((d)[2]), "+f"((d)[3]) \
        : "r"((a)[0]), "r"((a)[1]), "r"((a)[2]), "r"((a)[3]), \
          "r"(b0), "r"(b1))

static __device__ __forceinline__ uint32_t packh2(float x, float y) {
    __half2 h = __floats2half2_rn(x, y);
    return *reinterpret_cast<uint32_t*>(&h);
}

// synthesize the m16n8k16 A fragments for one k-step into a[2][4]
// rows: lane gid + {0,8,16,24}; freq cols per PTX layout {0,1,8,9}+16*kf+2*tig
static __device__ __forceinline__ void synthA(uint32_t a[2][4], const float* fq,
                                              int kf, bool useCos,
                                              float tv0, float tv1,
                                              float tv2, float tv3)
{
    const float Fa = fq[kf * 16 + 0], Fb = fq[kf * 16 + 1];
    const float Fc = fq[kf * 16 + 8], Fd = fq[kf * 16 + 9];
    if (!useCos) {
        a[0][0] = packh2(__sinf(tv0 * Fa), __sinf(tv0 * Fb));
        a[0][2] = packh2(__sinf(tv0 * Fc), __sinf(tv0 * Fd));
        a[0][1] = packh2(__sinf(tv1 * Fa), __sinf(tv1 * Fb));
        a[0][3] = packh2(__sinf(tv1 * Fc), __sinf(tv1 * Fd));
        a[1][0] = packh2(__sinf(tv2 * Fa), __sinf(tv2 * Fb));
        a[1][2] = packh2(__sinf(tv2 * Fc), __sinf(tv2 * Fd));
        a[1][1] = packh2(__sinf(tv3 * Fa), __sinf(tv3 * Fb));
        a[1][3] = packh2(__sinf(tv3 * Fc), __sinf(tv3 * Fd));
    } else {
        a[0][0] = packh2(__cosf(tv0 * Fa), __cosf(tv0 * Fb));
        a[0][2] = packh2(__cosf(tv0 * Fc), __cosf(tv0 * Fd));
        a[0][1] = packh2(__cosf(tv1 * Fa), __cosf(tv1 * Fb));
        a[0][3] = packh2(__cosf(tv1 * Fc), __cosf(tv1 * Fd));
        a[1][0] = packh2(__cosf(tv2 * Fa), __cosf(tv2 * Fb));
        a[1][2] = packh2(__cosf(tv2 * Fc), __cosf(tv2 * Fd));
        a[1][1] = packh2(__cosf(tv3 * Fa), __cosf(tv3 * Fb));
        a[1][3] = packh2(__cosf(tv3 * Fc), __cosf(tv3 * Fd));
    }
}

__global__ void __launch_bounds__(NT, 1)
fourier_mma_kernel(const float* __restrict__ t,
                   const float* __restrict__ freqs,
                   const float* __restrict__ As,
                   const float* __restrict__ Ac,
                   float* __restrict__ out,
                   int rows)
{
    extern __shared__ char smem[];
    char*  sW = smem;
    float* sF = (float*)(smem + SF_OFF);
    const uint32_t uW = smem_u32(sW);

    const int tid  = threadIdx.x;
    const int lane = tid & 31;
    const int wid  = tid >> 5;

    // ---- one-time: freqs (x 2pi) + W fp32->fp16 into swizzled SMEM --------
    if (tid < 128) sF[tid] = freqs[tid] * 6.283185307179586f;
    for (int i = tid; i < 256 * 64; i += NT) {
        const int n  = i >> 6;
        const int j4 = i & 63;
        const int k0 = j4 << 2;
        const float* src = (k0 < 128) ? (As + n * 128 + k0)
                                      : (Ac + n * 128 + (k0 - 128));
        const float4 w = *reinterpret_cast<const float4*>(src);
        uint32_t byte = swz((uint32_t)n, (uint32_t)(j4 >> 1)) + ((uint32_t)(j4 & 1) << 3);
        uint2 v;
        v.x = packh2(w.x, w.y);
        v.y = packh2(w.z, w.w);
        *reinterpret_cast<uint2*>(sW + byte) = v;
    }

    // ---- warp grid 4 (M) x 4 (N); warp tile 32 x 64 -----------------------
    const int wm  = wid >> 2;
    const int wn  = wid & 3;
    const int gid = lane >> 2, tig = lane & 3;
    const int bRowOff = (lane & 7) + ((lane >> 4) << 3);
    const int bHi     = (lane >> 3) & 1;
    const float* fq = sF + tig * 2;        // per-k-step: +16*kf, cols {0,1,8,9}

    const int numTiles = rows / MT;        // 2048
    const int stride   = gridDim.x;

    __syncthreads();                       // W + freqs visible

    for (int tile = blockIdx.x; tile < numTiles; tile += stride) {
        const int rbase = tile * MT + wm * 32 + gid;
        const float tv0 = t[rbase];
        const float tv1 = t[rbase + 8];
        const float tv2 = t[rbase + 16];
        const float tv3 = t[rbase + 24];

        float acc[2][8][4];
        #pragma unroll
        for (int mi = 0; mi < 2; mi++)
            #pragma unroll
            for (int ni = 0; ni < 8; ni++)
                #pragma unroll
                for (int q = 0; q < 4; q++) acc[mi][ni][q] = 0.0f;

        // A fragments double-buffered; synthesize step 0 up front
        uint32_t aB[2][2][4];
        synthA(aB[0], fq, 0, false, tv0, tv1, tv2, tv3);

        #pragma unroll 2
        for (int ks = 0; ks < 16; ks++) {
            const int cur = ks & 1;

            // ---- first B fragment (longest latency) -----------------------
            uint32_t bq[4];
            LDSM_X4(bq, uW + swz((uint32_t)(wn * 64 + bRowOff),
                                 (uint32_t)(ks * 2 + bHi)));

            // ---- synthesize NEXT step's A (independent of this step's MMA)
            if (ks < 15)
                synthA(aB[cur ^ 1], fq, (ks + 1) & 7, (ks + 1) >= 8,
                       tv0, tv1, tv2, tv3);

            // ---- 4 B tiles (16 N-cols each) + MMA --------------------------
            #pragma unroll
            for (int nt = 0; nt < 4; nt++) {
                #pragma unroll
                for (int mi = 0; mi < 2; mi++) {
                    MMA_16816(acc[mi][nt * 2],     aB[cur][mi], bq[0], bq[1]);
                    MMA_16816(acc[mi][nt * 2 + 1], aB[cur][mi], bq[2], bq[3]);
                }
                if (nt < 3) {
                    const uint32_t n =
                        (uint32_t)(wn * 64 + (nt + 1) * 16 + bRowOff);
                    LDSM_X4(bq, uW + swz(n, (uint32_t)(ks * 2 + bHi)));
                }
            }
        }

        // ---- epilogue: regs -> gmem (STG.64) ------------------------------
        #pragma unroll
        for (int mi = 0; mi < 2; mi++) {
            const size_t mrow = (size_t)(rbase + mi * 16);
            float* o0 = out + mrow * 256 + wn * 64 + tig * 2;
            #pragma unroll
            for (int ni = 0; ni < 8; ni++) {
                float2 v0, v1;
                v0.x = acc[mi][ni][0]; v0.y = acc[mi][ni][1];
                v1.x = acc[mi][ni][2]; v1.y = acc[mi][ni][3];
                *reinterpret_cast<float2*>(o0 + ni * 8)        = v0;  // row r
                *reinterpret_cast<float2*>(o0 + ni * 8 + 2048) = v1;  // row r+8
            }
        }
    }
}

extern "C" void kernel_launch(void* const* d_in, const int* in_sizes, int n_in,
                              void* d_out, int out_size)
{
    const float* t     = (const float*)d_in[0];
    const float* freqs = (const float*)d_in[1];
    const float* As    = (const float*)d_in[2];
    const float* Ac    = (const float*)d_in[3];
    float* out         = (float*)d_out;

    int sm_count = 148;
    cudaDeviceGetAttribute(&sm_count, cudaDevAttrMultiProcessorCount, 0);
    cudaFuncSetAttribute(fourier_mma_kernel,
                         cudaFuncAttributeMaxDynamicSharedMemorySize, SMEM_TOTAL);

    const int rows = in_sizes[0];          // B*L = 262144
    fourier_mma_kernel<<<sm_count, NT, SMEM_TOTAL>>>(t, freqs, As, Ac, out, rows);
}

// round 15
// speedup vs baseline: 1.5324x; 1.1671x over previous
#include <cuda_runtime.h>
#include <cuda_fp16.h>
#include <cstdint>

// ---------------------------------------------------------------------------
// out[m, c] = sum_f sin(2*pi*f*t[m])*As[c,f] + cos(2*pi*f*t[m])*Ac[c,f]
// GEMM: M = 262144, N = 256, K = 256 (K = [sin | cos] halves).
// R15: R14 with the cos-half ping-pong parity FIXED (R14 consumed the buffer
// it had just overwritten). Design: register-synthesized A, 512 thr,
// 4 warps/SMSP, warp tile 32x64, no barriers;
//  - k-halves PAIRED: one theta + __sincosf feeds both the sin k-step (ksp)
//    and the cos k-step (ksp+8) -> halves FMUL and freq loads.
//  - 2-deep B ping-pong across the pair's 8 B-subtiles.
//  - hoisted swizzle addressing (per-pair XOR offset + per-nt bases).
// ---------------------------------------------------------------------------

#define NT        512
#define MT        128                    // rows per CTA iteration
#define SF_OFF    131072
#define SMEM_TOTAL (131072 + 512)        // W (256x256 fp16) + freqs

static __device__ __forceinline__ uint32_t smem_u32(const void* p) {
    uint32_t a;
    asm("{ .reg .u64 t; cvta.to.shared.u64 t, %1; cvt.u32.u64 %0, t; }"
        : "=r"(a) : "l"(p));
    return a;
}

// byte offset of (row, 16B-chunk) in a 512 B/row tile with XOR swizzle:
// chunk' = chunk ^ (row & 7). Conflict-free for ldmatrix and the fills.
static __device__ __forceinline__ uint32_t swz(uint32_t row, uint32_t chunk) {
    return row * 512u + ((chunk ^ (row & 7u)) << 4);
}

#define LDSM_X4(r, addr) \
    asm volatile("ldmatrix.sync.aligned.m8n8.x4.shared.b16 {%0,%1,%2,%3}, [%4];" \
        : "=r"((r)[0]), "=r"((r)[1]), "=r"((r)[2]), "=r"((r)[3]) : "r"(addr))

#define MMA_16816(d, a, b0, b1) \
    asm volatile("mma.sync.aligned.m16n8k16.row.col.f32.f16.f16.f32 " \
        "{%0,%1,%2,%3}, {%4,%5,%6,%7}, {%8,%9}, {%0,%1,%2,%3};" \
        : "+f"((d)[0]), "+f"((d)[1]), "+f"((d)[2]), "+f"((d)[3]) \
        : "r"((a)[0]), "r"((a)[1]), "r"((a)[2]), "r"((a)[3]), \
          "r"(b0), "r"(b1))

static __device__ __forceinline__ uint32_t packh2(float x, float y) {
    __half2 h = __floats2half2_rn(x, y);
    return *reinterpret_cast<uint32_t*>(&h);
}

__global__ void __launch_bounds__(NT, 1)
fourier_mma_kernel(const float* __restrict__ t,
                   const float* __restrict__ freqs,
                   const float* __restrict__ As,
                   const float* __restrict__ Ac,
                   float* __restrict__ out,
                   int rows)
{
    extern __shared__ char smem[];
    char*  sW = smem;
    float* sF = (float*)(smem + SF_OFF);
    const uint32_t uW = smem_u32(sW);

    const int tid  = threadIdx.x;
    const int lane = tid & 31;
    const int wid  = tid >> 5;

    // ---- one-time: freqs (x 2pi) + W fp32->fp16 into swizzled SMEM --------
    if (tid < 128) sF[tid] = freqs[tid] * 6.283185307179586f;
    for (int i = tid; i < 256 * 64; i += NT) {
        const int n  = i >> 6;
        const int j4 = i & 63;
        const int k0 = j4 << 2;
        const float* src = (k0 < 128) ? (As + n * 128 + k0)
                                      : (Ac + n * 128 + (k0 - 128));
        const float4 w = *reinterpret_cast<const float4*>(src);
        uint32_t byte = swz((uint32_t)n, (uint32_t)(j4 >> 1)) + ((uint32_t)(j4 & 1) << 3);
        uint2 v;
        v.x = packh2(w.x, w.y);
        v.y = packh2(w.z, w.w);
        *reinterpret_cast<uint2*>(sW + byte) = v;
    }

    // ---- warp grid 4 (M) x 4 (N); warp tile 32 x 64 -----------------------
    const int wm  = wid >> 2;
    const int wn  = wid & 3;
    const int gid = lane >> 2, tig = lane & 3;
    const int bRowOff = (lane & 7) + ((lane >> 4) << 3);
    const int bHi     = (lane >> 3) & 1;
    const uint32_t r7 = (uint32_t)(lane & 7);   // row&7, same for all B rows
    const float* fq = sF + tig * 2;        // per-pair: +16*kf, cols {0,1,8,9}

    // per-nt B base addresses (swizzle XOR applied separately per k-step)
    uint32_t baseB[4];
    #pragma unroll
    for (int nt = 0; nt < 4; nt++)
        baseB[nt] = uW + (uint32_t)(wn * 64 + nt * 16 + bRowOff) * 512u;

    const int numTiles = rows / MT;        // 2048
    const int stride   = gridDim.x;

    __syncthreads();                       // W + freqs visible

    for (int tile = blockIdx.x; tile < numTiles; tile += stride) {
        const int rbase = tile * MT + wm * 32 + gid;
        const float tv0 = t[rbase];
        const float tv1 = t[rbase + 8];
        const float tv2 = t[rbase + 16];
        const float tv3 = t[rbase + 24];

        float acc[2][8][4];
        #pragma unroll
        for (int mi = 0; mi < 2; mi++)
            #pragma unroll
            for (int ni = 0; ni < 8; ni++)
                #pragma unroll
                for (int q = 0; q < 4; q++) acc[mi][ni][q] = 0.0f;

        #pragma unroll 2
        for (int ksp = 0; ksp < 8; ksp++) {
            // swizzled chunk offsets for the sin (k=ksp) and cos (k=ksp+8)
            const uint32_t offS = (((uint32_t)(ksp * 2 + bHi)      ^ r7) << 4);
            const uint32_t offC = (((uint32_t)(ksp * 2 + 16 + bHi) ^ r7) << 4);

            // ---- first sin-B fragment (longest latency) -------------------
            uint32_t bq[2][4];
            LDSM_X4(bq[0], baseB[0] + offS);

            // ---- synthesize sin AND cos A frags from ONE theta ------------
            const float Fa = fq[ksp * 16 + 0], Fb = fq[ksp * 16 + 1];
            const float Fc = fq[ksp * 16 + 8], Fd = fq[ksp * 16 + 9];
            uint32_t aS[2][4], aC[2][4];
            {
                float s0, c0, s1, c1, s2, c2, s3, c3;
                // row tv0
                __sincosf(tv0 * Fa, &s0, &c0); __sincosf(tv0 * Fb, &s1, &c1);
                __sincosf(tv0 * Fc, &s2, &c2); __sincosf(tv0 * Fd, &s3, &c3);
                aS[0][0] = packh2(s0, s1); aC[0][0] = packh2(c0, c1);
                aS[0][2] = packh2(s2, s3); aC[0][2] = packh2(c2, c3);
                // row tv1
                __sincosf(tv1 * Fa, &s0, &c0); __sincosf(tv1 * Fb, &s1, &c1);
                __sincosf(tv1 * Fc, &s2, &c2); __sincosf(tv1 * Fd, &s3, &c3);
                aS[0][1] = packh2(s0, s1); aC[0][1] = packh2(c0, c1);
                aS[0][3] = packh2(s2, s3); aC[0][3] = packh2(c2, c3);
                // row tv2
                __sincosf(tv2 * Fa, &s0, &c0); __sincosf(tv2 * Fb, &s1, &c1);
                __sincosf(tv2 * Fc, &s2, &c2); __sincosf(tv2 * Fd, &s3, &c3);
                aS[1][0] = packh2(s0, s1); aC[1][0] = packh2(c0, c1);
                aS[1][2] = packh2(s2, s3); aC[1][2] = packh2(c2, c3);
                // row tv3
                __sincosf(tv3 * Fa, &s0, &c0); __sincosf(tv3 * Fb, &s1, &c1);
                __sincosf(tv3 * Fc, &s2, &c2); __sincosf(tv3 * Fd, &s3, &c3);
                aS[1][1] = packh2(s0, s1); aC[1][1] = packh2(c0, c1);
                aS[1][3] = packh2(s2, s3); aC[1][3] = packh2(c2, c3);
            }

            // ---- sin half: consume bq[nt&1], prefetch bq[(nt+1)&1] --------
            #pragma unroll
            for (int nt = 0; nt < 4; nt++) {
                // prefetch: next sin tile, or first cos tile after the last
                if (nt < 3) LDSM_X4(bq[(nt + 1) & 1], baseB[nt + 1] + offS);
                else        LDSM_X4(bq[(nt + 1) & 1], baseB[0] + offC);
                const uint32_t* bb = bq[nt & 1];
                #pragma unroll
                for (int mi = 0; mi < 2; mi++) {
                    MMA_16816(acc[mi][nt * 2],     aS[mi], bb[0], bb[1]);
                    MMA_16816(acc[mi][nt * 2 + 1], aS[mi], bb[2], bb[3]);
                }
            }
            // ---- cos half: SAME parity (cos tile 0 landed in bq[0]) -------
            #pragma unroll
            for (int nt = 0; nt < 4; nt++) {
                if (nt < 3) LDSM_X4(bq[(nt + 1) & 1], baseB[nt + 1] + offC);
                const uint32_t* bb = bq[nt & 1];
                #pragma unroll
                for (int mi = 0; mi < 2; mi++) {
                    MMA_16816(acc[mi][nt * 2],     aC[mi], bb[0], bb[1]);
                    MMA_16816(acc[mi][nt * 2 + 1], aC[mi], bb[2], bb[3]);
                }
            }
        }

        // ---- epilogue: regs -> gmem (STG.64) ------------------------------
        #pragma unroll
        for (int mi = 0; mi < 2; mi++) {
            const size_t mrow = (size_t)(rbase + mi * 16);
            float* o0 = out + mrow * 256 + wn * 64 + tig * 2;
            #pragma unroll
            for (int ni = 0; ni < 8; ni++) {
                float2 v0, v1;
                v0.x = acc[mi][ni][0]; v0.y = acc[mi][ni][1];
                v1.x = acc[mi][ni][2]; v1.y = acc[mi][ni][3];
                *reinterpret_cast<float2*>(o0 + ni * 8)        = v0;  // row r
                *reinterpret_cast<float2*>(o0 + ni * 8 + 2048) = v1;  // row r+8
            }
        }
    }
}

extern "C" void kernel_launch(void* const* d_in, const int* in_sizes, int n_in,
                              void* d_out, int out_size)
{
    const float* t     = (const float*)d_in[0];
    const float* freqs = (const float*)d_in[1];
    const float* As    = (const float*)d_in[2];
    const float* Ac    = (const float*)d_in[3];
    float* out         = (float*)d_out;

    int sm_count = 148;
    cudaDeviceGetAttribute(&sm_count, cudaDevAttrMultiProcessorCount, 0);
    cudaFuncSetAttribute(fourier_mma_kernel,
                         cudaFuncAttributeMaxDynamicSharedMemorySize, SMEM_TOTAL);

    const int rows = in_sizes[0];          // B*L = 262144
    fourier_mma_kernel<<<sm_count, NT, SMEM_TOTAL>>>(t, freqs, As, Ac, out, rows);
}